// round 1
// baseline (speedup 1.0000x reference)
#include <cuda_runtime.h>
#include <cuda_bf16.h>
#include <math.h>

// RoPE: x[B=16, S=8192, D=128] fp32. Reference uses pos = arange(S) (token_positions ignored).
// angle(p, f) = p * theta^(-2f/128), pairs are interleaved (x[2f], x[2f+1]).
//
// Strategy: split p = p_hi*64 + p_lo. Precompute float2 (cos,sin) tables for
// p_lo*w_f (64x64) and 64*p_hi*w_f (128x64) in double precision, then combine
// per element with the angle-addition formula. Main kernel is pure fp32
// streaming: one float4 (= 2 rotation pairs) per thread.

#define S_LEN   8192
#define HALF    64          // number of frequencies = D/2
#define PLO     64
#define PHI     128         // S / PLO

__device__ float2 g_lo[PLO * HALF];   // [p_lo][f]
__device__ float2 g_hi[PHI * HALF];   // [p_hi][f]

__global__ void rope_fill_tables() {
    int t = blockIdx.x * blockDim.x + threadIdx.x;
    const double LOG2_THETA = 13.287712379549449;   // log2(10000)
    if (t < PLO * HALF) {
        int p = t / HALF;
        int f = t % HALF;
        // inv_freq computed like the reference: theta^(-(2f)/128), rounded to fp32
        double w = exp2(-((2.0 * (double)f) / 128.0) * LOG2_THETA);
        float wf = (float)w;
        double ang = (double)p * (double)wf;
        g_lo[t] = make_float2((float)cos(ang), (float)sin(ang));
    } else if (t < PLO * HALF + PHI * HALF) {
        int u = t - PLO * HALF;
        int p = u / HALF;
        int f = u % HALF;
        double w = exp2(-((2.0 * (double)f) / 128.0) * LOG2_THETA);
        float wf = (float)w;
        double ang = (double)(p * PLO) * (double)wf;
        g_hi[u] = make_float2((float)cos(ang), (float)sin(ang));
    }
}

__global__ void __launch_bounds__(256) rope_apply(
    const float4* __restrict__ x, float4* __restrict__ out, int n4)
{
    int i = blockIdx.x * blockDim.x + threadIdx.x;
    if (i >= n4) return;

    float4 v = x[i];

    int d4    = i & 31;            // 32 float4 per token (D=128)
    int token = i >> 5;
    int pos   = token & (S_LEN - 1);
    int plo   = pos & (PLO - 1);
    int phi   = pos >> 6;
    int f0    = d4 * 2;

    float2 lo0 = g_lo[plo * HALF + f0];
    float2 hi0 = g_hi[phi * HALF + f0];
    float2 lo1 = g_lo[plo * HALF + f0 + 1];
    float2 hi1 = g_hi[phi * HALF + f0 + 1];

    // angle addition: (c,s) for p_hi*64*w + p_lo*w
    float c0 = hi0.x * lo0.x - hi0.y * lo0.y;
    float s0 = hi0.x * lo0.y + hi0.y * lo0.x;
    float c1 = hi1.x * lo1.x - hi1.y * lo1.y;
    float s1 = hi1.x * lo1.y + hi1.y * lo1.x;

    float4 o;
    o.x = v.x * c0 - v.y * s0;
    o.y = v.x * s0 + v.y * c0;
    o.z = v.z * c1 - v.w * s1;
    o.w = v.z * s1 + v.w * c1;

    out[i] = o;
}

extern "C" void kernel_launch(void* const* d_in, const int* in_sizes, int n_in,
                              void* d_out, int out_size) {
    const float4* x = (const float4*)d_in[0];
    float4* out = (float4*)d_out;

    // Fill trig tables (12288 entries)
    int fill_n = PLO * HALF + PHI * HALF;
    rope_fill_tables<<<(fill_n + 255) / 256, 256>>>();

    int n4 = out_size / 4;   // total float4s = B*S*D/4 = 4,194,304
    rope_apply<<<(n4 + 255) / 256, 256>>>(x, out, n4);
}

// round 2
// speedup vs baseline: 1.3556x; 1.3556x over previous
#include <cuda_runtime.h>
#include <cuda_bf16.h>
#include <math.h>

// RoPE: x[B=16, S=8192, D=128] fp32, interleaved pairs, pos = arange(S)
// (the token_positions input is ignored by the reference).
//
// Kernel 1 (trivial): fill 64 inv_freq values in double precision.
// Kernel 2: block = 4 consecutive positions x 16 batches x 32 float4.
//   - 256 threads compute sincosf(pos * inv_freq[f]) -> smem (4x64 float2)
//   - all 512 threads stream 4 independent float4 in/out (MLP=4)
//   - trig read back as one LDS.128 per float4 (c0,s0,c1,s1)

#define B_      16
#define S_      8192
#define HALF    64
#define JPOS    4
#define THREADS 512

__device__ float g_invfreq[HALF];

__global__ void fill_invfreq() {
    int f = threadIdx.x;
    if (f < HALF) {
        const double LOG2_THETA = 13.287712379549449;  // log2(10000)
        double w = exp2(-((2.0 * (double)f) / 128.0) * LOG2_THETA);
        g_invfreq[f] = (float)w;
    }
}

__global__ void __launch_bounds__(THREADS) rope_apply(
    const float4* __restrict__ x, float4* __restrict__ out)
{
    __shared__ float2 s_trig[JPOS][HALF];   // [pos-in-block][freq] = (cos,sin)

    int t  = threadIdx.x;
    int p0 = blockIdx.x * JPOS;

    int batch = t >> 5;            // 0..15
    int d4    = t & 31;            // float4 index within head dim
    size_t base = (size_t)batch * (S_ * 32) + (size_t)p0 * 32 + d4;

    // Front-batch 4 independent 16B loads (one per position)
    float4 v[JPOS];
#pragma unroll
    for (int j = 0; j < JPOS; j++) v[j] = x[base + (size_t)j * 32];

    // 256 threads compute the 4x64 trig table for this block's positions
    if (t < JPOS * HALF) {
        int j = t >> 6;            // 0..3
        int f = t & 63;            // 0..63
        float ang = (float)(p0 + j) * g_invfreq[f];
        float s, c;
        sincosf(ang, &s, &c);
        s_trig[j][f] = make_float2(c, s);
    }
    __syncthreads();

#pragma unroll
    for (int j = 0; j < JPOS; j++) {
        // (cos_{2*d4}, sin_{2*d4}, cos_{2*d4+1}, sin_{2*d4+1}) in one LDS.128
        float4 cs = reinterpret_cast<const float4*>(s_trig[j])[d4];
        float4 o;
        o.x = v[j].x * cs.x - v[j].y * cs.y;
        o.y = v[j].x * cs.y + v[j].y * cs.x;
        o.z = v[j].z * cs.z - v[j].w * cs.w;
        o.w = v[j].z * cs.w + v[j].w * cs.z;
        out[base + (size_t)j * 32] = o;
    }
}

extern "C" void kernel_launch(void* const* d_in, const int* in_sizes, int n_in,
                              void* d_out, int out_size) {
    const float4* x = (const float4*)d_in[0];
    float4* out = (float4*)d_out;

    fill_invfreq<<<1, HALF>>>();
    rope_apply<<<S_ / JPOS, THREADS>>>(x, out);   // 2048 blocks
}

// round 3
// speedup vs baseline: 1.3983x; 1.0315x over previous
#include <cuda_runtime.h>
#include <cuda_bf16.h>
#include <math.h>

// RoPE: x[B=16, S=8192, D=128] fp32, interleaved pairs, pos = arange(S)
// (token_positions is ignored by the reference).
//
// Single fused kernel. Block = 4 positions x 16 batches x 32 float4:
//   - 512 threads front-batch 4 independent float4 loads (one per position)
//   - threads t<64 compute w_f = theta^(-f/64) via double exp2 (correctly
//     rounded to the reference's fp32 inv_freq), then 4x sincosf -> smem
//   - after one barrier, all threads rotate + store with streaming hints.

#define B_      16
#define S_      8192
#define HALF    64
#define JPOS    4
#define THREADS 512

__global__ void __launch_bounds__(THREADS) rope_apply(
    const float4* __restrict__ x, float4* __restrict__ out)
{
    __shared__ float2 s_trig[JPOS][HALF];   // [pos-in-block][freq] = (cos,sin)

    int t  = threadIdx.x;
    int p0 = blockIdx.x * JPOS;

    int batch = t >> 5;            // 0..15
    int d4    = t & 31;            // float4 index within head dim
    size_t base = (size_t)batch * (S_ * 32) + (size_t)p0 * 32 + d4;

    // Front-batch 4 independent 16B streaming loads (one per position)
    float4 v[JPOS];
#pragma unroll
    for (int j = 0; j < JPOS; j++)
        v[j] = __ldcs(&x[base + (size_t)j * 32]);

    // 2 warps compute the 4x64 trig table while the loads are in flight
    if (t < HALF) {
        const double LOG2_THETA = 13.287712379549449;  // log2(10000)
        double w = exp2(-((2.0 * (double)t) / 128.0) * LOG2_THETA);
        float wf = (float)w;       // == reference's fp32 inv_freq[t]
#pragma unroll
        for (int j = 0; j < JPOS; j++) {
            float ang = (float)(p0 + j) * wf;
            float s, c;
            sincosf(ang, &s, &c);
            s_trig[j][t] = make_float2(c, s);
        }
    }
    __syncthreads();

#pragma unroll
    for (int j = 0; j < JPOS; j++) {
        // (cos_{2*d4}, sin_{2*d4}, cos_{2*d4+1}, sin_{2*d4+1}) in one LDS.128
        float4 cs = reinterpret_cast<const float4*>(s_trig[j])[d4];
        float4 o;
        o.x = v[j].x * cs.x - v[j].y * cs.y;
        o.y = v[j].x * cs.y + v[j].y * cs.x;
        o.z = v[j].z * cs.z - v[j].w * cs.w;
        o.w = v[j].z * cs.w + v[j].w * cs.z;
        __stcs(&out[base + (size_t)j * 32], o);
    }
}

extern "C" void kernel_launch(void* const* d_in, const int* in_sizes, int n_in,
                              void* d_out, int out_size) {
    const float4* x = (const float4*)d_in[0];
    float4* out = (float4*)d_out;

    rope_apply<<<S_ / JPOS, THREADS>>>(x, out);   // 2048 blocks, single launch
}